// round 7
// baseline (speedup 1.0000x reference)
#include <cuda_runtime.h>
#include <cstdint>
#include <cstdio>

#define NTOK  131072
#define DIM   128
#define NCODE 1024
#define NLVL  4

#define BM   128
#define BKC  128
#define DC   32              // d-chunk width
#define NDC  (DIM / DC)      // 4
#define TM   8
#define TN   8

#define ARGMIN_GRID (NTOK / BM)                  // 1024
#define RES_GRID    (NTOK * (DIM / 4) / 256)     // 16384
#define FINAL_ROWS  16
#define FINAL_GRID  (NTOK / FINAL_ROWS)          // 8192

// ---------------------------------------------------------------------------
// argmin: register-tiled fp32 GEMM + binned argmin. Static smem only
// (36.5 KB). en2 for all codes computed in-kernel (embedding is L2-resident).
// NO device globals, NO doubles.
// ---------------------------------------------------------------------------
__global__ void __launch_bounds__(256)
argmin_kernel(const float* __restrict__ src,     // N x D (inputs or residual)
              const float* __restrict__ embed,   // K x D, this level
              float* __restrict__ idx_out,       // N floats, this level slice
              int early)
{
    if (early) return;

    __shared__ float Rs[DC * BM];     // 16 KB, chunk-local, XOR-swizzled
    __shared__ float Es[DC * BKC];    // 16 KB
    __shared__ float rn2s[BM];        // 0.5 KB
    __shared__ float en2s[NCODE];     // 4 KB

    const int tid   = threadIdx.x;
    const int m0blk = blockIdx.x * BM;
    const float4* __restrict__ src4 =
        reinterpret_cast<const float4*>(src) + (size_t)m0blk * (DIM / 4);
    const float4* __restrict__ emb4 = reinterpret_cast<const float4*>(embed);

    // ---- rn2 per row + en2 per code (XLA-style fmul/fadd + shfl tree) ----
    {
        int w = tid >> 5, lane = tid & 31;
        for (int r = w; r < BM; r += 8) {
            float4 v = src4[(size_t)r * (DIM / 4) + lane];
            float p = __fadd_rn(__fadd_rn(__fadd_rn(__fmul_rn(v.x, v.x),
                                                    __fmul_rn(v.y, v.y)),
                                          __fmul_rn(v.z, v.z)),
                                __fmul_rn(v.w, v.w));
            #pragma unroll
            for (int off = 16; off >= 1; off >>= 1)
                p = __fadd_rn(p, __shfl_down_sync(0xffffffffu, p, off));
            if (lane == 0) rn2s[r] = p;
        }
        for (int r = w; r < NCODE; r += 8) {
            float4 v = emb4[(size_t)r * (DIM / 4) + lane];
            float p = __fadd_rn(__fadd_rn(__fadd_rn(__fmul_rn(v.x, v.x),
                                                    __fmul_rn(v.y, v.y)),
                                          __fmul_rn(v.z, v.z)),
                                __fmul_rn(v.w, v.w));
            #pragma unroll
            for (int off = 16; off >= 1; off >>= 1)
                p = __fadd_rn(p, __shfl_down_sync(0xffffffffu, p, off));
            if (lane == 0) en2s[r] = p;
        }
    }

    const int ty = tid >> 4, tx = tid & 15;
    const int m0 = ty * TM, k0 = tx * TN;
    const int gR = m0 >> 2, gE = k0 >> 2;

    float bestv[TM];
    int   bestk[TM];
    #pragma unroll
    for (int i = 0; i < TM; i++) { bestv[i] = __int_as_float(0x7f800000); bestk[i] = 0; }

    for (int ct = 0; ct < NCODE / BKC; ct++) {
        float acc[TM][TN];
        #pragma unroll
        for (int i = 0; i < TM; i++)
            #pragma unroll
            for (int j = 0; j < TN; j++) acc[i][j] = 0.f;

        for (int dc = 0; dc < NDC; dc++) {
            __syncthreads();   // previous chunk fully consumed
            #pragma unroll
            for (int i = 0; i < 4; i++) {
                int flat = tid + i * 256;
                int m = flat >> 3, dv = flat & 7;
                int g = m >> 2, mi = m & 3;
                int col = ((g ^ dv) << 2) | mi;
                float4 r4 = src4[(size_t)m * (DIM / 4) + dc * 8 + dv];
                Rs[(4 * dv + 0) * BM + col] = r4.x;
                Rs[(4 * dv + 1) * BM + col] = r4.y;
                Rs[(4 * dv + 2) * BM + col] = r4.z;
                Rs[(4 * dv + 3) * BM + col] = r4.w;
                float4 e4 = emb4[((size_t)ct * BKC + m) * (DIM / 4) + dc * 8 + dv];
                Es[(4 * dv + 0) * BKC + col] = e4.x;
                Es[(4 * dv + 1) * BKC + col] = e4.y;
                Es[(4 * dv + 2) * BKC + col] = e4.z;
                Es[(4 * dv + 3) * BKC + col] = e4.w;
            }
            __syncthreads();

            #pragma unroll
            for (int dv = 0; dv < 8; dv++) {
                int oR0 = ((gR       ^ dv) << 2);
                int oR1 = (((gR + 1) ^ dv) << 2);
                int oE0 = ((gE       ^ dv) << 2);
                int oE1 = (((gE + 1) ^ dv) << 2);
                #pragma unroll
                for (int jj = 0; jj < 4; jj++) {
                    int dl = 4 * dv + jj;
                    float4 ra = *reinterpret_cast<const float4*>(&Rs[dl * BM  + oR0]);
                    float4 rb = *reinterpret_cast<const float4*>(&Rs[dl * BM  + oR1]);
                    float4 ea = *reinterpret_cast<const float4*>(&Es[dl * BKC + oE0]);
                    float4 eb = *reinterpret_cast<const float4*>(&Es[dl * BKC + oE1]);
                    acc[0][0]=fmaf(ra.x,ea.x,acc[0][0]); acc[0][1]=fmaf(ra.x,ea.y,acc[0][1]);
                    acc[0][2]=fmaf(ra.x,ea.z,acc[0][2]); acc[0][3]=fmaf(ra.x,ea.w,acc[0][3]);
                    acc[0][4]=fmaf(ra.x,eb.x,acc[0][4]); acc[0][5]=fmaf(ra.x,eb.y,acc[0][5]);
                    acc[0][6]=fmaf(ra.x,eb.z,acc[0][6]); acc[0][7]=fmaf(ra.x,eb.w,acc[0][7]);
                    acc[1][0]=fmaf(ra.y,ea.x,acc[1][0]); acc[1][1]=fmaf(ra.y,ea.y,acc[1][1]);
                    acc[1][2]=fmaf(ra.y,ea.z,acc[1][2]); acc[1][3]=fmaf(ra.y,ea.w,acc[1][3]);
                    acc[1][4]=fmaf(ra.y,eb.x,acc[1][4]); acc[1][5]=fmaf(ra.y,eb.y,acc[1][5]);
                    acc[1][6]=fmaf(ra.y,eb.z,acc[1][6]); acc[1][7]=fmaf(ra.y,eb.w,acc[1][7]);
                    acc[2][0]=fmaf(ra.z,ea.x,acc[2][0]); acc[2][1]=fmaf(ra.z,ea.y,acc[2][1]);
                    acc[2][2]=fmaf(ra.z,ea.z,acc[2][2]); acc[2][3]=fmaf(ra.z,ea.w,acc[2][3]);
                    acc[2][4]=fmaf(ra.z,eb.x,acc[2][4]); acc[2][5]=fmaf(ra.z,eb.y,acc[2][5]);
                    acc[2][6]=fmaf(ra.z,eb.z,acc[2][6]); acc[2][7]=fmaf(ra.z,eb.w,acc[2][7]);
                    acc[3][0]=fmaf(ra.w,ea.x,acc[3][0]); acc[3][1]=fmaf(ra.w,ea.y,acc[3][1]);
                    acc[3][2]=fmaf(ra.w,ea.z,acc[3][2]); acc[3][3]=fmaf(ra.w,ea.w,acc[3][3]);
                    acc[3][4]=fmaf(ra.w,eb.x,acc[3][4]); acc[3][5]=fmaf(ra.w,eb.y,acc[3][5]);
                    acc[3][6]=fmaf(ra.w,eb.z,acc[3][6]); acc[3][7]=fmaf(ra.w,eb.w,acc[3][7]);
                    acc[4][0]=fmaf(rb.x,ea.x,acc[4][0]); acc[4][1]=fmaf(rb.x,ea.y,acc[4][1]);
                    acc[4][2]=fmaf(rb.x,ea.z,acc[4][2]); acc[4][3]=fmaf(rb.x,ea.w,acc[4][3]);
                    acc[4][4]=fmaf(rb.x,eb.x,acc[4][4]); acc[4][5]=fmaf(rb.x,eb.y,acc[4][5]);
                    acc[4][6]=fmaf(rb.x,eb.z,acc[4][6]); acc[4][7]=fmaf(rb.x,eb.w,acc[4][7]);
                    acc[5][0]=fmaf(rb.y,ea.x,acc[5][0]); acc[5][1]=fmaf(rb.y,ea.y,acc[5][1]);
                    acc[5][2]=fmaf(rb.y,ea.z,acc[5][2]); acc[5][3]=fmaf(rb.y,ea.w,acc[5][3]);
                    acc[5][4]=fmaf(rb.y,eb.x,acc[5][4]); acc[5][5]=fmaf(rb.y,eb.y,acc[5][5]);
                    acc[5][6]=fmaf(rb.y,eb.z,acc[5][6]); acc[5][7]=fmaf(rb.y,eb.w,acc[5][7]);
                    acc[6][0]=fmaf(rb.z,ea.x,acc[6][0]); acc[6][1]=fmaf(rb.z,ea.y,acc[6][1]);
                    acc[6][2]=fmaf(rb.z,ea.z,acc[6][2]); acc[6][3]=fmaf(rb.z,ea.w,acc[6][3]);
                    acc[6][4]=fmaf(rb.z,eb.x,acc[6][4]); acc[6][5]=fmaf(rb.z,eb.y,acc[6][5]);
                    acc[6][6]=fmaf(rb.z,eb.z,acc[6][6]); acc[6][7]=fmaf(rb.z,eb.w,acc[6][7]);
                    acc[7][0]=fmaf(rb.w,ea.x,acc[7][0]); acc[7][1]=fmaf(rb.w,ea.y,acc[7][1]);
                    acc[7][2]=fmaf(rb.w,ea.z,acc[7][2]); acc[7][3]=fmaf(rb.w,ea.w,acc[7][3]);
                    acc[7][4]=fmaf(rb.w,eb.x,acc[7][4]); acc[7][5]=fmaf(rb.w,eb.y,acc[7][5]);
                    acc[7][6]=fmaf(rb.w,eb.z,acc[7][6]); acc[7][7]=fmaf(rb.w,eb.w,acc[7][7]);
                }
            }
        }

        // ---- epilogue: dist = fl(fl(rn2+en2) - 2*dot), lowest-index argmin ----
        #pragma unroll
        for (int i = 0; i < TM; i++) {
            float r2 = rn2s[m0 + i];
            float lv = __int_as_float(0x7f800000);
            int   lk = 0;
            #pragma unroll
            for (int j = 0; j < TN; j++) {
                int kk = ct * BKC + k0 + j;
                float t1   = __fadd_rn(r2, en2s[kk]);
                float dist = __fsub_rn(t1, __fmul_rn(2.0f, acc[i][j]));
                if (dist < lv) { lv = dist; lk = kk; }
            }
            #pragma unroll
            for (int off = 8; off >= 1; off >>= 1) {
                float ov = __shfl_xor_sync(0xffffffffu, lv, off);
                int   ok = __shfl_xor_sync(0xffffffffu, lk, off);
                if (ov < lv || (ov == lv && ok < lk)) { lv = ov; lk = ok; }
            }
            if (lv < bestv[i]) { bestv[i] = lv; bestk[i] = lk; }
            else if (lv == bestv[i] && lk < bestk[i]) bestk[i] = lk;
        }
    }

    if (tx == 0) {
        #pragma unroll
        for (int i = 0; i < TM; i++)
            idx_out[m0blk + m0 + i] = (float)bestk[i];
    }
}

// ---------------------------------------------------------------------------
// residual: dst = src - gather(e[idx]), exact fsub. dst may alias src.
// ---------------------------------------------------------------------------
__global__ void __launch_bounds__(256)
residual_kernel(const float* __restrict__ src,
                const float* __restrict__ embed,     // K x D, this level
                const float* __restrict__ idx_lvl,   // N floats, this level
                float* __restrict__ dst,
                int early)
{
    if (early) return;
    int i = blockIdx.x * 256 + threadIdx.x;   // float4 index
    int row = i >> 5, c = i & 31;
    int k = __float2int_rn(idx_lvl[row]);
    float4 v = reinterpret_cast<const float4*>(src)[i];
    float4 e = reinterpret_cast<const float4*>(embed + (size_t)k * DIM)[c];
    v.x = __fsub_rn(v.x, e.x);
    v.y = __fsub_rn(v.y, e.y);
    v.z = __fsub_rn(v.z, e.z);
    v.w = __fsub_rn(v.w, e.w);
    reinterpret_cast<float4*>(dst)[i] = v;
}

// ---------------------------------------------------------------------------
__global__ void init3_kernel(float* __restrict__ out3, int early)
{
    if (early) return;
    if (threadIdx.x < 3) out3[threadIdx.x] = 0.f;
}

// ---------------------------------------------------------------------------
// final fused pass: rebuild chain from indices, overwrite out_q with the
// straight-through result, accumulate total loss sum via ONE float atomic.
// ---------------------------------------------------------------------------
__global__ void __launch_bounds__(256)
final_kernel(const float* __restrict__ inputs,
             const float* __restrict__ embedding,   // L*K*D
             const float* __restrict__ idx_all,     // L*N floats
             float* __restrict__ out_q,
             float* __restrict__ out3,
             int early)
{
    if (early) return;
    __shared__ float red[256];

    int tid = threadIdx.x;
    int d   = tid & 127;
    float acc = 0.f;

    #pragma unroll
    for (int it = 0; it < FINAL_ROWS / 2; it++) {
        int row = blockIdx.x * FINAL_ROWS + it * 2 + (tid >> 7);
        size_t o = (size_t)row * DIM + d;
        float inp = inputs[o];
        float r = inp, qs, e, diff;
        int k;

        k = __float2int_rn(idx_all[row]);
        e = embedding[((size_t)0 * NCODE + k) * DIM + d];
        diff = __fsub_rn(e, r); acc = fmaf(diff, diff, acc);
        qs = e; r = __fsub_rn(r, e);

        k = __float2int_rn(idx_all[(size_t)1 * NTOK + row]);
        e = embedding[((size_t)1 * NCODE + k) * DIM + d];
        diff = __fsub_rn(e, r); acc = fmaf(diff, diff, acc);
        qs = __fadd_rn(qs, e); r = __fsub_rn(r, e);

        k = __float2int_rn(idx_all[(size_t)2 * NTOK + row]);
        e = embedding[((size_t)2 * NCODE + k) * DIM + d];
        diff = __fsub_rn(e, r); acc = fmaf(diff, diff, acc);
        qs = __fadd_rn(qs, e); r = __fsub_rn(r, e);

        k = __float2int_rn(idx_all[(size_t)3 * NTOK + row]);
        e = embedding[((size_t)3 * NCODE + k) * DIM + d];
        diff = __fsub_rn(e, r); acc = fmaf(diff, diff, acc);
        qs = __fadd_rn(qs, e);

        out_q[o] = __fadd_rn(inp, __fsub_rn(qs, inp));
    }

    red[tid] = acc;
    __syncthreads();
    #pragma unroll
    for (int s = 128; s > 0; s >>= 1) {
        if (tid < s) red[tid] += red[tid + s];
        __syncthreads();
    }
    if (tid == 0) atomicAdd(&out3[1], red[0]);
}

// ---------------------------------------------------------------------------
__global__ void scalars_kernel(float* __restrict__ out3, int early)
{
    if (early) return;
    if (threadIdx.x == 0) {
        // total raw sum / (N*D); N*D = 2^24 so the scale is exact
        float cb = __fmul_rn(out3[1], 1.0f / 16777216.0f);
        out3[0] = __fadd_rn(cb, __fmul_rn(0.25f, cb));  // vq = cb + 0.25*commit
        out3[1] = cb;                                   // codebook
        out3[2] = cb;                                   // commit (identical)
    }
}

// ---------------------------------------------------------------------------
// Static-init diagnostics + priming (production geometry).
// ---------------------------------------------------------------------------
namespace {
struct ModuleEagerLoad {
    ModuleEagerLoad() {
        cudaFree(0);
        size_t f0 = 0, f1 = 0, tot = 0;
        cudaMemGetInfo(&f0, &tot);

        argmin_kernel<<<ARGMIN_GRID, 256>>>(nullptr, nullptr, nullptr, 1);
        residual_kernel<<<RES_GRID, 256>>>(nullptr, nullptr, nullptr, nullptr, 1);
        init3_kernel<<<1, 32>>>(nullptr, 1);
        final_kernel<<<FINAL_GRID, 256>>>(nullptr, nullptr, nullptr, nullptr, nullptr, 1);
        scalars_kernel<<<1, 32>>>(nullptr, 1);
        cudaDeviceSynchronize();

        cudaMemGetInfo(&f1, &tot);
        fprintf(stderr, "[eager] free before=%zu after=%zu delta=%lld\n",
                f0, f1, (long long)f0 - (long long)f1);
    }
};
static ModuleEagerLoad s_eager_load;
}  // namespace

// ---------------------------------------------------------------------------
extern "C" void kernel_launch(void* const* d_in, const int* in_sizes, int n_in,
                              void* d_out, int out_size)
{
    const float* inputs    = (const float*)d_in[0];
    const float* embedding = (const float*)d_in[1];

    float* out     = (float*)d_out;
    float* out_q   = out;                            // N*D: residual scratch, then quantized_sum
    float* out_idx = out + (size_t)NTOK * DIM;       // L*N indices (as f32)
    float* out3    = out_idx + (size_t)NLVL * NTOK;  // vq, codebook, commit

    size_t fa = 0, fb = 0, tot = 0;
    cudaMemGetInfo(&fa, &tot);

    init3_kernel<<<1, 32>>>(out3, 0);
    for (int lvl = 0; lvl < NLVL; lvl++) {
        const float* emb_l = embedding + (size_t)lvl * NCODE * DIM;
        const float* src   = (lvl == 0) ? inputs : out_q;
        argmin_kernel<<<ARGMIN_GRID, 256>>>(
            src, emb_l, out_idx + (size_t)lvl * NTOK, 0);
        if (lvl < NLVL - 1)
            residual_kernel<<<RES_GRID, 256>>>(
                src, emb_l, out_idx + (size_t)lvl * NTOK, out_q, 0);
    }
    final_kernel<<<FINAL_GRID, 256>>>(inputs, embedding, out_idx, out_q, out3, 0);
    scalars_kernel<<<1, 32>>>(out3, 0);

    cudaMemGetInfo(&fb, &tot);
    fprintf(stderr, "[kl] free entry=%zu exit=%zu delta=%lld\n",
            fa, fb, (long long)fa - (long long)fb);
}

// round 10
// speedup vs baseline: 1.0090x; 1.0090x over previous
#include <cuda_runtime.h>
#include <cstdint>
#include <cstdio>

#define NTOK  131072
#define DIM   128
#define NCODE 1024
#define NLVL  4

#define BM    64                 // tokens per CTA
#define ARGMIN_GRID (NTOK / BM)  // 2048
#define RES_GRID    (NTOK * (DIM / 4) / 256)     // 16384
#define FINAL_ROWS  16
#define FINAL_GRID  (NTOK / FINAL_ROWS)          // 8192

#define MARGIN 1e-5f             // candidate capture margin (>> mma error 3e-8)

// ---- legacy tensor-core mma (sm_80+; compiles on sm_100 base) ----
#define MMA_TF32(d, a, b0, b1)                                              \
    asm volatile("mma.sync.aligned.m16n8k8.row.col.f32.tf32.tf32.f32 "      \
        "{%0,%1,%2,%3}, {%4,%5,%6,%7}, {%8,%9}, {%0,%1,%2,%3};"             \
        : "+f"((d)[0]), "+f"((d)[1]), "+f"((d)[2]), "+f"((d)[3])            \
        : "r"((a)[0]), "r"((a)[1]), "r"((a)[2]), "r"((a)[3]),               \
          "r"(b0), "r"(b1))

__device__ __forceinline__ void tf32_split(float x, uint32_t& hi, uint32_t& lo)
{
    asm("cvt.rna.tf32.f32 %0, %1;" : "=r"(hi) : "f"(x));
    float r = __fsub_rn(x, __uint_as_float(hi));
    asm("cvt.rna.tf32.f32 %0, %1;" : "=r"(lo) : "f"(r));
}

// exact R7-bit-identical rescore: sequential-d fp32 fmaf dot + binned dist,
// lowest-index tie-break via packed u64 atomicMin.
__device__ __forceinline__ void rescore(const float (*As)[132],
                                        const float* __restrict__ embed,
                                        const float* en2s, const float* rn2s,
                                        unsigned long long* cand,
                                        int row, int k)
{
    const float4* e4 = reinterpret_cast<const float4*>(embed + (size_t)k * DIM);
    float dot = 0.f;
    #pragma unroll 8
    for (int i = 0; i < 32; i++) {
        float4 e = __ldg(e4 + i);
        dot = fmaf(As[row][4 * i + 0], e.x, dot);
        dot = fmaf(As[row][4 * i + 1], e.y, dot);
        dot = fmaf(As[row][4 * i + 2], e.z, dot);
        dot = fmaf(As[row][4 * i + 3], e.w, dot);
    }
    float dist = __fsub_rn(__fadd_rn(rn2s[row], en2s[k]), __fmul_rn(2.0f, dot));
    unsigned long long p =
        ((unsigned long long)__float_as_uint(dist) << 32) | (unsigned)k;
    atomicMin(cand + row, p);
}

// ---------------------------------------------------------------------------
// argmin: 3xTF32 mma.sync GEMM (approximate) + exact candidate rescoring.
// Static smem ~40 KB. No globals, no doubles, no opt-in attributes.
// ---------------------------------------------------------------------------
__global__ void __launch_bounds__(128)
argmin_kernel(const float* __restrict__ src,     // N x D (inputs or residual)
              const float* __restrict__ embed,   // K x D, this level (fp32)
              float* __restrict__ idx_out,       // N floats, this level slice
              int early)
{
    if (early) return;

    __shared__ float As[BM][132];                // 33.8 KB, full K resident
    __shared__ float en2s[NCODE];                // 4 KB
    __shared__ float rn2s[BM];
    __shared__ float redv[4][BM];                // per-warp approx min value
    __shared__ float minv[BM];                   // per-token approx min
    __shared__ unsigned long long cand[BM];      // packed (dist,idx) winner

    const int tid  = threadIdx.x;
    const int wid  = tid >> 5, lane = tid & 31;
    const int m0blk = blockIdx.x * BM;
    const float4* __restrict__ src4 =
        reinterpret_cast<const float4*>(src) + (size_t)m0blk * (DIM / 4);
    const float4* __restrict__ emb4 = reinterpret_cast<const float4*>(embed);

    // ---- A panel -> smem (coalesced float4) ----
    #pragma unroll
    for (int i = 0; i < 16; i++) {
        int flat = tid + i * 128;
        int row = flat >> 5, c4 = flat & 31;
        float4 v = src4[(size_t)row * (DIM / 4) + c4];
        As[row][c4 * 4 + 0] = v.x;
        As[row][c4 * 4 + 1] = v.y;
        As[row][c4 * 4 + 2] = v.z;
        As[row][c4 * 4 + 3] = v.w;
    }

    // ---- rn2 / en2: bit-identical to the validated R7 kernel ----
    for (int r = wid; r < BM; r += 4) {
        float4 v = src4[(size_t)r * (DIM / 4) + lane];
        float p = __fadd_rn(__fadd_rn(__fadd_rn(__fmul_rn(v.x, v.x),
                                                __fmul_rn(v.y, v.y)),
                                      __fmul_rn(v.z, v.z)),
                            __fmul_rn(v.w, v.w));
        #pragma unroll
        for (int off = 16; off >= 1; off >>= 1)
            p = __fadd_rn(p, __shfl_down_sync(0xffffffffu, p, off));
        if (lane == 0) rn2s[r] = p;
    }
    for (int r = wid; r < NCODE; r += 4) {
        float4 v = emb4[(size_t)r * (DIM / 4) + lane];
        float p = __fadd_rn(__fadd_rn(__fadd_rn(__fmul_rn(v.x, v.x),
                                                __fmul_rn(v.y, v.y)),
                                      __fmul_rn(v.z, v.z)),
                            __fmul_rn(v.w, v.w));
        #pragma unroll
        for (int off = 16; off >= 1; off >>= 1)
            p = __fadd_rn(p, __shfl_down_sync(0xffffffffu, p, off));
        if (lane == 0) en2s[r] = p;
    }
    if (tid < BM) cand[tid] = ~0ull;
    __syncthreads();

    const int r_lane = lane >> 2;   // 0..7
    const int c_lane = lane & 3;    // 0..3
    const int n_warp0 = wid * 256;  // this warp's code range

    // per-thread TOP-2 over the codes this thread scores
    float b1v[4][2], b2v[4][2];
    int   b1k[4][2], b2k[4][2];
    #pragma unroll
    for (int mt = 0; mt < 4; mt++)
        #pragma unroll
        for (int h = 0; h < 2; h++) {
            b1v[mt][h] = __int_as_float(0x7f800000); b1k[mt][h] = 0;
            b2v[mt][h] = __int_as_float(0x7f800000); b2k[mt][h] = 0;
        }

    for (int nblk = 0; nblk < 8; nblk++) {
        const int n0 = n_warp0 + nblk * 32;

        float acc[4][4][4];   // [nt][mt][frag]
        #pragma unroll
        for (int nt = 0; nt < 4; nt++)
            #pragma unroll
            for (int mt = 0; mt < 4; mt++)
                #pragma unroll
                for (int q = 0; q < 4; q++) acc[nt][mt][q] = 0.f;

        #pragma unroll 4
        for (int ks = 0; ks < 16; ks++) {
            const int k0 = ks * 8;
            uint32_t aH[4][4], aL[4][4];
            #pragma unroll
            for (int mt = 0; mt < 4; mt++) {
                int r0 = mt * 16 + r_lane;
                tf32_split(As[r0    ][k0 + c_lane    ], aH[mt][0], aL[mt][0]);
                tf32_split(As[r0 + 8][k0 + c_lane    ], aH[mt][1], aL[mt][1]);
                tf32_split(As[r0    ][k0 + c_lane + 4], aH[mt][2], aL[mt][2]);
                tf32_split(As[r0 + 8][k0 + c_lane + 4], aH[mt][3], aL[mt][3]);
            }
            #pragma unroll
            for (int nt = 0; nt < 4; nt++) {
                int code = n0 + nt * 8 + r_lane;
                const float* ep = embed + (size_t)code * DIM + k0 + c_lane;
                float b0f = __ldg(ep);
                float b1f = __ldg(ep + 4);
                uint32_t bh0, bl0, bh1, bl1;
                tf32_split(b0f, bh0, bl0);
                tf32_split(b1f, bh1, bl1);
                #pragma unroll
                for (int mt = 0; mt < 4; mt++) {
                    MMA_TF32(acc[nt][mt], aH[mt], bh0, bh1);   // hi*hi
                    MMA_TF32(acc[nt][mt], aH[mt], bl0, bl1);   // hi*lo
                    MMA_TF32(acc[nt][mt], aL[mt], bh0, bh1);   // lo*hi
                }
            }
        }

        // ---- approx epilogue with top-2 tracking (ascending code order) ----
        #pragma unroll
        for (int nt = 0; nt < 4; nt++) {
            int kk0 = n0 + nt * 8 + 2 * c_lane;
            #pragma unroll
            for (int mt = 0; mt < 4; mt++) {
                int rlo = mt * 16 + r_lane;
                float r2a = rn2s[rlo];
                float r2b = rn2s[rlo + 8];
                #pragma unroll
                for (int q = 0; q < 4; q++) {
                    int   h  = q >> 1;                 // 0: row rlo, 1: row rlo+8
                    int   kk = kk0 + (q & 1);
                    float r2 = h ? r2b : r2a;
                    float t  = __fsub_rn(__fadd_rn(r2, en2s[kk]),
                                         __fmul_rn(2.0f, acc[nt][mt][q]));
                    if (t < b1v[mt][h]) {
                        b2v[mt][h] = b1v[mt][h]; b2k[mt][h] = b1k[mt][h];
                        b1v[mt][h] = t;          b1k[mt][h] = kk;
                    } else if (t < b2v[mt][h]) {
                        b2v[mt][h] = t;          b2k[mt][h] = kk;
                    }
                }
            }
        }
    }

    // ---- per-warp approx min value per token row ----
    #pragma unroll
    for (int mt = 0; mt < 4; mt++)
        #pragma unroll
        for (int h = 0; h < 2; h++) {
            float v = b1v[mt][h];
            #pragma unroll
            for (int off = 1; off <= 2; off <<= 1) {
                float ov = __shfl_xor_sync(0xffffffffu, v, off);
                if (ov < v) v = ov;
            }
            if (c_lane == 0) redv[wid][mt * 16 + r_lane + 8 * h] = v;
        }
    __syncthreads();

    if (tid < BM) {
        float v = redv[0][tid];
        #pragma unroll
        for (int w = 1; w < 4; w++) v = fminf(v, redv[w][tid]);
        minv[tid] = v;
    }
    __syncthreads();

    // ---- exact rescoring of all candidates within MARGIN of approx min ----
    #pragma unroll
    for (int mt = 0; mt < 4; mt++)
        #pragma unroll
        for (int h = 0; h < 2; h++) {
            int row = mt * 16 + r_lane + 8 * h;
            float cut = minv[row] + MARGIN;
            if (b1v[mt][h] <= cut)
                rescore(As, embed, en2s, rn2s, cand, row, b1k[mt][h]);
            if (b2v[mt][h] <= cut && b2k[mt][h] != b1k[mt][h])
                rescore(As, embed, en2s, rn2s, cand, row, b2k[mt][h]);
        }
    __syncthreads();

    if (tid < BM)
        idx_out[m0blk + tid] = (float)(unsigned)(cand[tid] & 0xFFFFFFFFull);
}

// ---------------------------------------------------------------------------
// residual: dst = src - gather(e[idx]), exact fsub. dst may alias src.
// ---------------------------------------------------------------------------
__global__ void __launch_bounds__(256)
residual_kernel(const float* __restrict__ src,
                const float* __restrict__ embed,
                const float* __restrict__ idx_lvl,
                float* __restrict__ dst,
                int early)
{
    if (early) return;
    int i = blockIdx.x * 256 + threadIdx.x;
    int row = i >> 5, c = i & 31;
    int k = __float2int_rn(idx_lvl[row]);
    float4 v = reinterpret_cast<const float4*>(src)[i];
    float4 e = reinterpret_cast<const float4*>(embed + (size_t)k * DIM)[c];
    v.x = __fsub_rn(v.x, e.x);
    v.y = __fsub_rn(v.y, e.y);
    v.z = __fsub_rn(v.z, e.z);
    v.w = __fsub_rn(v.w, e.w);
    reinterpret_cast<float4*>(dst)[i] = v;
}

__global__ void init3_kernel(float* __restrict__ out3, int early)
{
    if (early) return;
    if (threadIdx.x < 3) out3[threadIdx.x] = 0.f;
}

// ---------------------------------------------------------------------------
// final fused pass (unchanged from the validated R7 kernel)
// ---------------------------------------------------------------------------
__global__ void __launch_bounds__(256)
final_kernel(const float* __restrict__ inputs,
             const float* __restrict__ embedding,
             const float* __restrict__ idx_all,
             float* __restrict__ out_q,
             float* __restrict__ out3,
             int early)
{
    if (early) return;
    __shared__ float red[256];

    int tid = threadIdx.x;
    int d   = tid & 127;
    float acc = 0.f;

    #pragma unroll
    for (int it = 0; it < FINAL_ROWS / 2; it++) {
        int row = blockIdx.x * FINAL_ROWS + it * 2 + (tid >> 7);
        size_t o = (size_t)row * DIM + d;
        float inp = inputs[o];
        float r = inp, qs, e, diff;
        int k;

        k = __float2int_rn(idx_all[row]);
        e = embedding[((size_t)0 * NCODE + k) * DIM + d];
        diff = __fsub_rn(e, r); acc = fmaf(diff, diff, acc);
        qs = e; r = __fsub_rn(r, e);

        k = __float2int_rn(idx_all[(size_t)1 * NTOK + row]);
        e = embedding[((size_t)1 * NCODE + k) * DIM + d];
        diff = __fsub_rn(e, r); acc = fmaf(diff, diff, acc);
        qs = __fadd_rn(qs, e); r = __fsub_rn(r, e);

        k = __float2int_rn(idx_all[(size_t)2 * NTOK + row]);
        e = embedding[((size_t)2 * NCODE + k) * DIM + d];
        diff = __fsub_rn(e, r); acc = fmaf(diff, diff, acc);
        qs = __fadd_rn(qs, e); r = __fsub_rn(r, e);

        k = __float2int_rn(idx_all[(size_t)3 * NTOK + row]);
        e = embedding[((size_t)3 * NCODE + k) * DIM + d];
        diff = __fsub_rn(e, r); acc = fmaf(diff, diff, acc);
        qs = __fadd_rn(qs, e);

        out_q[o] = __fadd_rn(inp, __fsub_rn(qs, inp));
    }

    red[tid] = acc;
    __syncthreads();
    #pragma unroll
    for (int s = 128; s > 0; s >>= 1) {
        if (tid < s) red[tid] += red[tid + s];
        __syncthreads();
    }
    if (tid == 0) atomicAdd(&out3[1], red[0]);
}

__global__ void scalars_kernel(float* __restrict__ out3, int early)
{
    if (early) return;
    if (threadIdx.x == 0) {
        float cb = __fmul_rn(out3[1], 1.0f / 16777216.0f);
        out3[0] = __fadd_rn(cb, __fmul_rn(0.25f, cb));
        out3[1] = cb;
        out3[2] = cb;
    }
}

// ---------------------------------------------------------------------------
namespace {
struct ModuleEagerLoad {
    ModuleEagerLoad() {
        cudaFree(0);
        size_t f0 = 0, f1 = 0, tot = 0;
        cudaMemGetInfo(&f0, &tot);

        argmin_kernel<<<ARGMIN_GRID, 128>>>(nullptr, nullptr, nullptr, 1);
        residual_kernel<<<RES_GRID, 256>>>(nullptr, nullptr, nullptr, nullptr, 1);
        init3_kernel<<<1, 32>>>(nullptr, 1);
        final_kernel<<<FINAL_GRID, 256>>>(nullptr, nullptr, nullptr, nullptr, nullptr, 1);
        scalars_kernel<<<1, 32>>>(nullptr, 1);
        cudaDeviceSynchronize();

        cudaMemGetInfo(&f1, &tot);
        fprintf(stderr, "[eager] free before=%zu after=%zu delta=%lld\n",
                f0, f1, (long long)f0 - (long long)f1);
    }
};
static ModuleEagerLoad s_eager_load;
}  // namespace

// ---------------------------------------------------------------------------
extern "C" void kernel_launch(void* const* d_in, const int* in_sizes, int n_in,
                              void* d_out, int out_size)
{
    const float* inputs    = (const float*)d_in[0];
    const float* embedding = (const float*)d_in[1];

    float* out     = (float*)d_out;
    float* out_q   = out;                            // N*D: residual scratch, then quantized_sum
    float* out_idx = out + (size_t)NTOK * DIM;       // L*N indices (as f32)
    float* out3    = out_idx + (size_t)NLVL * NTOK;  // vq, codebook, commit

    init3_kernel<<<1, 32>>>(out3, 0);
    for (int lvl = 0; lvl < NLVL; lvl++) {
        const float* emb_l = embedding + (size_t)lvl * NCODE * DIM;
        const float* src   = (lvl == 0) ? inputs : out_q;
        argmin_kernel<<<ARGMIN_GRID, 128>>>(
            src, emb_l, out_idx + (size_t)lvl * NTOK, 0);
        if (lvl < NLVL - 1)
            residual_kernel<<<RES_GRID, 256>>>(
                src, emb_l, out_idx + (size_t)lvl * NTOK, out_q, 0);
    }
    final_kernel<<<FINAL_GRID, 256>>>(inputs, embedding, out_idx, out_q, out3, 0);
    scalars_kernel<<<1, 32>>>(out3, 0);
}

// round 11
// speedup vs baseline: 1.4723x; 1.4591x over previous
#include <cuda_runtime.h>
#include <cstdint>
#include <cstdio>

#define NTOK  131072
#define DIM   128
#define NCODE 1024
#define NLVL  4

#define BM    64                 // tokens per CTA
#define ARGMIN_GRID (NTOK / BM)  // 2048
#define RES_GRID    (NTOK * (DIM / 4) / 256)     // 16384
#define FINAL_ROWS  16
#define FINAL_GRID  (NTOK / FINAL_ROWS)          // 8192

#define MARGIN 4e-5f             // capture margin: 8x the 1xTF32 dist error

// ---- legacy tensor-core mma (sm_80+; compiles on sm_100 base) ----
#define MMA_TF32(d, a, b0, b1)                                              \
    asm volatile("mma.sync.aligned.m16n8k8.row.col.f32.tf32.tf32.f32 "      \
        "{%0,%1,%2,%3}, {%4,%5,%6,%7}, {%8,%9}, {%0,%1,%2,%3};"             \
        : "+f"((d)[0]), "+f"((d)[1]), "+f"((d)[2]), "+f"((d)[3])            \
        : "r"((a)[0]), "r"((a)[1]), "r"((a)[2]), "r"((a)[3]),               \
          "r"(b0), "r"(b1))

__device__ __forceinline__ uint32_t tf32_of(float x)
{
    uint32_t h;
    asm("cvt.rna.tf32.f32 %0, %1;" : "=r"(h) : "f"(x));
    return h;
}

// exact R7-bit-identical rescore: sequential-d fp32 fmaf dot (from GLOBAL
// exact src, L2-hot) + binned dist; lowest-index tie-break via u64 atomicMin.
__device__ __forceinline__ void rescore(const float4* __restrict__ srow4,
                                        const float* __restrict__ embed,
                                        const float* en2s, const float* rn2s,
                                        unsigned long long* cand,
                                        int row, int k)
{
    const float4* e4 = reinterpret_cast<const float4*>(embed + (size_t)k * DIM);
    float dot = 0.f;
    #pragma unroll 8
    for (int i = 0; i < 32; i++) {
        float4 a = __ldg(srow4 + i);
        float4 e = __ldg(e4 + i);
        dot = fmaf(a.x, e.x, dot);
        dot = fmaf(a.y, e.y, dot);
        dot = fmaf(a.z, e.z, dot);
        dot = fmaf(a.w, e.w, dot);
    }
    float dist = __fsub_rn(__fadd_rn(rn2s[row], en2s[k]), __fmul_rn(2.0f, dot));
    unsigned long long p =
        ((unsigned long long)__float_as_uint(dist) << 32) | (unsigned)k;
    atomicMin(cand + row, p);
}

// ---------------------------------------------------------------------------
// argmin: 1xTF32 mma.sync GEMM (approximate, A pre-rounded in smem) + exact
// candidate rescoring. Static smem ~40 KB. No globals, doubles, attributes.
// ---------------------------------------------------------------------------
__global__ void __launch_bounds__(128)
argmin_kernel(const float* __restrict__ src,     // N x D (inputs or residual)
              const float* __restrict__ embed,   // K x D, this level (fp32)
              float* __restrict__ idx_out,       // N floats, this level slice
              int early)
{
    if (early) return;

    __shared__ float As[BM][132];                // 33.8 KB, tf32-ROUNDED panel
    __shared__ float en2s[NCODE];                // 4 KB
    __shared__ float rn2s[BM];
    __shared__ float redv[4][BM];                // per-warp approx min value
    __shared__ float minv[BM];                   // per-token approx min
    __shared__ unsigned long long cand[BM];      // packed (dist,idx) winner

    const int tid  = threadIdx.x;
    const int wid  = tid >> 5, lane = tid & 31;
    const int m0blk = blockIdx.x * BM;
    const float4* __restrict__ src4 =
        reinterpret_cast<const float4*>(src) + (size_t)m0blk * (DIM / 4);
    const float4* __restrict__ emb4 = reinterpret_cast<const float4*>(embed);

    // ---- A panel -> smem, PRE-ROUNDED to tf32 (mma reads raw bits, no cvt) ----
    #pragma unroll
    for (int i = 0; i < 16; i++) {
        int flat = tid + i * 128;
        int row = flat >> 5, c4 = flat & 31;
        float4 v = src4[(size_t)row * (DIM / 4) + c4];
        As[row][c4 * 4 + 0] = __uint_as_float(tf32_of(v.x));
        As[row][c4 * 4 + 1] = __uint_as_float(tf32_of(v.y));
        As[row][c4 * 4 + 2] = __uint_as_float(tf32_of(v.z));
        As[row][c4 * 4 + 3] = __uint_as_float(tf32_of(v.w));
    }

    // ---- rn2 / en2 from EXACT global values: bit-identical to R7 ----
    for (int r = wid; r < BM; r += 4) {
        float4 v = src4[(size_t)r * (DIM / 4) + lane];
        float p = __fadd_rn(__fadd_rn(__fadd_rn(__fmul_rn(v.x, v.x),
                                                __fmul_rn(v.y, v.y)),
                                      __fmul_rn(v.z, v.z)),
                            __fmul_rn(v.w, v.w));
        #pragma unroll
        for (int off = 16; off >= 1; off >>= 1)
            p = __fadd_rn(p, __shfl_down_sync(0xffffffffu, p, off));
        if (lane == 0) rn2s[r] = p;
    }
    for (int r = wid; r < NCODE; r += 4) {
        float4 v = emb4[(size_t)r * (DIM / 4) + lane];
        float p = __fadd_rn(__fadd_rn(__fadd_rn(__fmul_rn(v.x, v.x),
                                                __fmul_rn(v.y, v.y)),
                                      __fmul_rn(v.z, v.z)),
                            __fmul_rn(v.w, v.w));
        #pragma unroll
        for (int off = 16; off >= 1; off >>= 1)
            p = __fadd_rn(p, __shfl_down_sync(0xffffffffu, p, off));
        if (lane == 0) en2s[r] = p;
    }
    if (tid < BM) cand[tid] = ~0ull;
    __syncthreads();

    const int r_lane = lane >> 2;   // 0..7
    const int c_lane = lane & 3;    // 0..3
    const int n_warp0 = wid * 256;  // this warp's code range

    // per-thread TOP-2 over the codes this thread scores
    float b1v[4][2], b2v[4][2];
    int   b1k[4][2], b2k[4][2];
    #pragma unroll
    for (int mt = 0; mt < 4; mt++)
        #pragma unroll
        for (int h = 0; h < 2; h++) {
            b1v[mt][h] = __int_as_float(0x7f800000); b1k[mt][h] = 0;
            b2v[mt][h] = __int_as_float(0x7f800000); b2k[mt][h] = 0;
        }

    for (int nblk = 0; nblk < 8; nblk++) {
        const int n0 = n_warp0 + nblk * 32;

        float acc[4][4][4];   // [nt][mt][frag]
        #pragma unroll
        for (int nt = 0; nt < 4; nt++)
            #pragma unroll
            for (int mt = 0; mt < 4; mt++)
                #pragma unroll
                for (int q = 0; q < 4; q++) acc[nt][mt][q] = 0.f;

        #pragma unroll 4
        for (int ks = 0; ks < 16; ks++) {
            const int k0 = ks * 8;
            // ---- A fragments: raw bit loads from pre-rounded panel ----
            uint32_t aH[4][4];
            #pragma unroll
            for (int mt = 0; mt < 4; mt++) {
                int r0 = mt * 16 + r_lane;
                aH[mt][0] = __float_as_uint(As[r0    ][k0 + c_lane    ]);
                aH[mt][1] = __float_as_uint(As[r0 + 8][k0 + c_lane    ]);
                aH[mt][2] = __float_as_uint(As[r0    ][k0 + c_lane + 4]);
                aH[mt][3] = __float_as_uint(As[r0 + 8][k0 + c_lane + 4]);
            }
            #pragma unroll
            for (int nt = 0; nt < 4; nt++) {
                int code = n0 + nt * 8 + r_lane;
                const float* ep = embed + (size_t)code * DIM + k0 + c_lane;
                uint32_t bh0 = tf32_of(__ldg(ep));
                uint32_t bh1 = tf32_of(__ldg(ep + 4));
                #pragma unroll
                for (int mt = 0; mt < 4; mt++)
                    MMA_TF32(acc[nt][mt], aH[mt], bh0, bh1);
            }
        }

        // ---- approx epilogue with top-2 tracking (ascending code order) ----
        #pragma unroll
        for (int nt = 0; nt < 4; nt++) {
            int kk0 = n0 + nt * 8 + 2 * c_lane;
            #pragma unroll
            for (int mt = 0; mt < 4; mt++) {
                int rlo = mt * 16 + r_lane;
                float r2a = rn2s[rlo];
                float r2b = rn2s[rlo + 8];
                #pragma unroll
                for (int q = 0; q < 4; q++) {
                    int   h  = q >> 1;
                    int   kk = kk0 + (q & 1);
                    float r2 = h ? r2b : r2a;
                    float t  = __fsub_rn(__fadd_rn(r2, en2s[kk]),
                                         __fmul_rn(2.0f, acc[nt][mt][q]));
                    if (t < b1v[mt][h]) {
                        b2v[mt][h] = b1v[mt][h]; b2k[mt][h] = b1k[mt][h];
                        b1v[mt][h] = t;          b1k[mt][h] = kk;
                    } else if (t < b2v[mt][h]) {
                        b2v[mt][h] = t;          b2k[mt][h] = kk;
                    }
                }
            }
        }
    }

    // ---- per-warp approx min value per token row ----
    #pragma unroll
    for (int mt = 0; mt < 4; mt++)
        #pragma unroll
        for (int h = 0; h < 2; h++) {
            float v = b1v[mt][h];
            #pragma unroll
            for (int off = 1; off <= 2; off <<= 1) {
                float ov = __shfl_xor_sync(0xffffffffu, v, off);
                if (ov < v) v = ov;
            }
            if (c_lane == 0) redv[wid][mt * 16 + r_lane + 8 * h] = v;
        }
    __syncthreads();

    if (tid < BM) {
        float v = redv[0][tid];
        #pragma unroll
        for (int w = 1; w < 4; w++) v = fminf(v, redv[w][tid]);
        minv[tid] = v;
    }
    __syncthreads();

    // ---- exact rescoring of all candidates within MARGIN of approx min ----
    #pragma unroll
    for (int mt = 0; mt < 4; mt++)
        #pragma unroll
        for (int h = 0; h < 2; h++) {
            int row = mt * 16 + r_lane + 8 * h;
            float cut = minv[row] + MARGIN;
            const float4* srow4 = src4 + (size_t)row * (DIM / 4);
            if (b1v[mt][h] <= cut)
                rescore(srow4, embed, en2s, rn2s, cand, row, b1k[mt][h]);
            if (b2v[mt][h] <= cut && b2k[mt][h] != b1k[mt][h])
                rescore(srow4, embed, en2s, rn2s, cand, row, b2k[mt][h]);
        }
    __syncthreads();

    if (tid < BM)
        idx_out[m0blk + tid] = (float)(unsigned)(cand[tid] & 0xFFFFFFFFull);
}

// ---------------------------------------------------------------------------
// residual: dst = src - gather(e[idx]), exact fsub. dst may alias src.
// ---------------------------------------------------------------------------
__global__ void __launch_bounds__(256)
residual_kernel(const float* __restrict__ src,
                const float* __restrict__ embed,
                const float* __restrict__ idx_lvl,
                float* __restrict__ dst,
                int early)
{
    if (early) return;
    int i = blockIdx.x * 256 + threadIdx.x;
    int row = i >> 5, c = i & 31;
    int k = __float2int_rn(idx_lvl[row]);
    float4 v = reinterpret_cast<const float4*>(src)[i];
    float4 e = reinterpret_cast<const float4*>(embed + (size_t)k * DIM)[c];
    v.x = __fsub_rn(v.x, e.x);
    v.y = __fsub_rn(v.y, e.y);
    v.z = __fsub_rn(v.z, e.z);
    v.w = __fsub_rn(v.w, e.w);
    reinterpret_cast<float4*>(dst)[i] = v;
}

__global__ void init3_kernel(float* __restrict__ out3, int early)
{
    if (early) return;
    if (threadIdx.x < 3) out3[threadIdx.x] = 0.f;
}

// ---------------------------------------------------------------------------
// final fused pass (unchanged from the validated R7 kernel)
// ---------------------------------------------------------------------------
__global__ void __launch_bounds__(256)
final_kernel(const float* __restrict__ inputs,
             const float* __restrict__ embedding,
             const float* __restrict__ idx_all,
             float* __restrict__ out_q,
             float* __restrict__ out3,
             int early)
{
    if (early) return;
    __shared__ float red[256];

    int tid = threadIdx.x;
    int d   = tid & 127;
    float acc = 0.f;

    #pragma unroll
    for (int it = 0; it < FINAL_ROWS / 2; it++) {
        int row = blockIdx.x * FINAL_ROWS + it * 2 + (tid >> 7);
        size_t o = (size_t)row * DIM + d;
        float inp = inputs[o];
        float r = inp, qs, e, diff;
        int k;

        k = __float2int_rn(idx_all[row]);
        e = embedding[((size_t)0 * NCODE + k) * DIM + d];
        diff = __fsub_rn(e, r); acc = fmaf(diff, diff, acc);
        qs = e; r = __fsub_rn(r, e);

        k = __float2int_rn(idx_all[(size_t)1 * NTOK + row]);
        e = embedding[((size_t)1 * NCODE + k) * DIM + d];
        diff = __fsub_rn(e, r); acc = fmaf(diff, diff, acc);
        qs = __fadd_rn(qs, e); r = __fsub_rn(r, e);

        k = __float2int_rn(idx_all[(size_t)2 * NTOK + row]);
        e = embedding[((size_t)2 * NCODE + k) * DIM + d];
        diff = __fsub_rn(e, r); acc = fmaf(diff, diff, acc);
        qs = __fadd_rn(qs, e); r = __fsub_rn(r, e);

        k = __float2int_rn(idx_all[(size_t)3 * NTOK + row]);
        e = embedding[((size_t)3 * NCODE + k) * DIM + d];
        diff = __fsub_rn(e, r); acc = fmaf(diff, diff, acc);
        qs = __fadd_rn(qs, e);

        out_q[o] = __fadd_rn(inp, __fsub_rn(qs, inp));
    }

    red[tid] = acc;
    __syncthreads();
    #pragma unroll
    for (int s = 128; s > 0; s >>= 1) {
        if (tid < s) red[tid] += red[tid + s];
        __syncthreads();
    }
    if (tid == 0) atomicAdd(&out3[1], red[0]);
}

__global__ void scalars_kernel(float* __restrict__ out3, int early)
{
    if (early) return;
    if (threadIdx.x == 0) {
        float cb = __fmul_rn(out3[1], 1.0f / 16777216.0f);
        out3[0] = __fadd_rn(cb, __fmul_rn(0.25f, cb));
        out3[1] = cb;
        out3[2] = cb;
    }
}

// ---------------------------------------------------------------------------
namespace {
struct ModuleEagerLoad {
    ModuleEagerLoad() {
        cudaFree(0);
        size_t f0 = 0, f1 = 0, tot = 0;
        cudaMemGetInfo(&f0, &tot);

        argmin_kernel<<<ARGMIN_GRID, 128>>>(nullptr, nullptr, nullptr, 1);
        residual_kernel<<<RES_GRID, 256>>>(nullptr, nullptr, nullptr, nullptr, 1);
        init3_kernel<<<1, 32>>>(nullptr, 1);
        final_kernel<<<FINAL_GRID, 256>>>(nullptr, nullptr, nullptr, nullptr, nullptr, 1);
        scalars_kernel<<<1, 32>>>(nullptr, 1);
        cudaDeviceSynchronize();

        cudaMemGetInfo(&f1, &tot);
        fprintf(stderr, "[eager] free before=%zu after=%zu delta=%lld\n",
                f0, f1, (long long)f0 - (long long)f1);
    }
};
static ModuleEagerLoad s_eager_load;
}  // namespace

// ---------------------------------------------------------------------------
extern "C" void kernel_launch(void* const* d_in, const int* in_sizes, int n_in,
                              void* d_out, int out_size)
{
    const float* inputs    = (const float*)d_in[0];
    const float* embedding = (const float*)d_in[1];

    float* out     = (float*)d_out;
    float* out_q   = out;                            // N*D: residual scratch, then quantized_sum
    float* out_idx = out + (size_t)NTOK * DIM;       // L*N indices (as f32)
    float* out3    = out_idx + (size_t)NLVL * NTOK;  // vq, codebook, commit

    init3_kernel<<<1, 32>>>(out3, 0);
    for (int lvl = 0; lvl < NLVL; lvl++) {
        const float* emb_l = embedding + (size_t)lvl * NCODE * DIM;
        const float* src   = (lvl == 0) ? inputs : out_q;
        argmin_kernel<<<ARGMIN_GRID, 128>>>(
            src, emb_l, out_idx + (size_t)lvl * NTOK, 0);
        if (lvl < NLVL - 1)
            residual_kernel<<<RES_GRID, 256>>>(
                src, emb_l, out_idx + (size_t)lvl * NTOK, out_q, 0);
    }
    final_kernel<<<FINAL_GRID, 256>>>(inputs, embedding, out_idx, out_q, out3, 0);
    scalars_kernel<<<1, 32>>>(out3, 0);
}

// round 12
// speedup vs baseline: 1.9890x; 1.3510x over previous
#include <cuda_runtime.h>
#include <cstdint>
#include <cstdio>

#define NTOK  131072
#define DIM   128
#define NCODE 1024
#define NLVL  4

#define BM    64                 // tokens per CTA
#define ARGMIN_GRID (NTOK / BM)  // 2048
#define RES_GRID    (NTOK * (DIM / 4) / 256)     // 16384
#define FINAL_ROWS  16
#define FINAL_GRID  (NTOK / FINAL_ROWS)          // 8192
#define PREP_GRID   (NLVL * NCODE / 8)           // 512

#define MARGIN 4e-5f             // capture margin: 8x the 1xTF32 dist error

#define LSTRIDE 260              // Aperm per-lane stride (words): 260 % 32 == 4

// ---- small float-only device global (experiment: no fp64 anywhere) ----
__device__ float g_en2[NLVL * NCODE];   // 16 KB

// ---- legacy tensor-core mma (sm_80+; compiles on sm_100 base) ----
#define MMA_TF32(d, a, b0, b1)                                              \
    asm volatile("mma.sync.aligned.m16n8k8.row.col.f32.tf32.tf32.f32 "      \
        "{%0,%1,%2,%3}, {%4,%5,%6,%7}, {%8,%9}, {%0,%1,%2,%3};"             \
        : "+f"((d)[0]), "+f"((d)[1]), "+f"((d)[2]), "+f"((d)[3])            \
        : "r"((a)[0]), "r"((a)[1]), "r"((a)[2]), "r"((a)[3]),               \
          "r"(b0), "r"(b1))

__device__ __forceinline__ uint32_t tf32_of(float x)
{
    uint32_t h;
    asm("cvt.rna.tf32.f32 %0, %1;" : "=r"(h) : "f"(x));
    return h;
}

__device__ __forceinline__ unsigned long long umin64(unsigned long long a,
                                                     unsigned long long b)
{ return a < b ? a : b; }
__device__ __forceinline__ unsigned long long umax64(unsigned long long a,
                                                     unsigned long long b)
{ return a > b ? a : b; }

// ---------------------------------------------------------------------------
// prep: en2[r] = sum_d e[r][d]^2 for ALL levels, once per launch.
// Formula bit-identical to the validated R7/R11 in-kernel version.
// ---------------------------------------------------------------------------
__global__ void __launch_bounds__(256)
prep_kernel(const float* __restrict__ embedding, int early)
{
    if (early) return;
    int lane = threadIdx.x & 31;
    int row  = blockIdx.x * 8 + (threadIdx.x >> 5);   // 0..4095
    float4 v = reinterpret_cast<const float4*>(embedding + (size_t)row * DIM)[lane];
    float p = __fadd_rn(__fadd_rn(__fadd_rn(__fmul_rn(v.x, v.x),
                                            __fmul_rn(v.y, v.y)),
                                  __fmul_rn(v.z, v.z)),
                        __fmul_rn(v.w, v.w));
    #pragma unroll
    for (int off = 16; off >= 1; off >>= 1)
        p = __fadd_rn(p, __shfl_down_sync(0xffffffffu, p, off));
    if (lane == 0) g_en2[row] = p;
}

// exact R7-bit-identical rescore: sequential-d fp32 fmaf dot (from GLOBAL
// exact src, L2-hot) + binned dist; lowest-index tie-break via u64 atomicMin.
__device__ __forceinline__ void rescore(const float4* __restrict__ srow4,
                                        const float* __restrict__ embed,
                                        const float* en2s, const float* rn2s,
                                        unsigned long long* cand,
                                        int row, int k)
{
    const float4* e4 = reinterpret_cast<const float4*>(embed + (size_t)k * DIM);
    float dot = 0.f;
    #pragma unroll 8
    for (int i = 0; i < 32; i++) {
        float4 a = __ldg(srow4 + i);
        float4 e = __ldg(e4 + i);
        dot = fmaf(a.x, e.x, dot);
        dot = fmaf(a.y, e.y, dot);
        dot = fmaf(a.z, e.z, dot);
        dot = fmaf(a.w, e.w, dot);
    }
    float dist = __fsub_rn(__fadd_rn(rn2s[row], en2s[k]), __fmul_rn(2.0f, dot));
    unsigned long long p =
        ((unsigned long long)__float_as_uint(dist) << 32) | (unsigned)k;
    atomicMin(cand + row, p);
}

// ---------------------------------------------------------------------------
// argmin: 1xTF32 mma.sync GEMM (A in fragment-major smem, LDS.128 broadcast)
// + exact candidate rescoring. Static smem ~40 KB.
// ---------------------------------------------------------------------------
__global__ void __launch_bounds__(128)
argmin_kernel(const float* __restrict__ src,     // N x D (inputs or residual)
              const float* __restrict__ embed,   // K x D, this level (fp32)
              const float* __restrict__ en2g,    // K, this level (from g_en2)
              float* __restrict__ idx_out,       // N floats, this level slice
              int early)
{
    if (early) return;

    __shared__ uint32_t Aperm[32 * LSTRIDE];     // 33.3 KB fragment-major tf32
    __shared__ float en2s[NCODE];                // 4 KB
    __shared__ float rn2s[BM];
    __shared__ unsigned long long redp[4][BM];   // per-warp packed approx min
    __shared__ float minv[BM];
    __shared__ unsigned long long cand[BM];

    const int tid  = threadIdx.x;
    const int wid  = tid >> 5, lane = tid & 31;
    const int m0blk = blockIdx.x * BM;
    const float4* __restrict__ src4 =
        reinterpret_cast<const float4*>(src) + (size_t)m0blk * (DIM / 4);

    // ---- en2 slice: global -> smem (coalesced float4) ----
    {
        const float4* g4 = reinterpret_cast<const float4*>(en2g);
        float4* s4 = reinterpret_cast<float4*>(en2s);
        for (int j = tid; j < NCODE / 4; j += 128) s4[j] = __ldg(g4 + j);
    }

    // ---- A panel -> Aperm (tf32-rounded, mma-fragment-major layout) ----
    #pragma unroll
    for (int i = 0; i < 16; i++) {
        int flat = tid + i * 128;
        int row = flat >> 5, c4 = flat & 31;
        float4 v = src4[(size_t)row * (DIM / 4) + c4];
        int ks = c4 >> 1, colhalf = c4 & 1;
        int r_lane = row & 7, rowhalf = (row >> 3) & 1, mt = row >> 4;
        int q = rowhalf + 2 * colhalf;
        int base = (r_lane * 4) * LSTRIDE + mt * 64 + ks * 4 + q;
        Aperm[base + 0 * LSTRIDE] = tf32_of(v.x);   // c_lane = 0..3
        Aperm[base + 1 * LSTRIDE] = tf32_of(v.y);
        Aperm[base + 2 * LSTRIDE] = tf32_of(v.z);
        Aperm[base + 3 * LSTRIDE] = tf32_of(v.w);
    }

    // ---- rn2 from EXACT global values: bit-identical to R7 ----
    for (int r = wid; r < BM; r += 4) {
        float4 v = src4[(size_t)r * (DIM / 4) + lane];
        float p = __fadd_rn(__fadd_rn(__fadd_rn(__fmul_rn(v.x, v.x),
                                                __fmul_rn(v.y, v.y)),
                                      __fmul_rn(v.z, v.z)),
                            __fmul_rn(v.w, v.w));
        #pragma unroll
        for (int off = 16; off >= 1; off >>= 1)
            p = __fadd_rn(p, __shfl_down_sync(0xffffffffu, p, off));
        if (lane == 0) rn2s[r] = p;
    }
    __syncthreads();

    const int r_lane = lane >> 2;   // 0..7
    const int c_lane = lane & 3;    // 0..3
    const int n_warp0 = wid * 256;  // this warp's code range

    // per-thread packed top-2 (value<<32 | idx): min packed = min dist, low idx
    unsigned long long b1[4][2], b2[4][2];
    #pragma unroll
    for (int mt = 0; mt < 4; mt++)
        #pragma unroll
        for (int h = 0; h < 2; h++) { b1[mt][h] = ~0ull; b2[mt][h] = ~0ull; }

    for (int nblk = 0; nblk < 8; nblk++) {
        const int n0 = n_warp0 + nblk * 32;

        float acc[4][4][4];   // [nt][mt][frag]
        #pragma unroll
        for (int nt = 0; nt < 4; nt++)
            #pragma unroll
            for (int mt = 0; mt < 4; mt++)
                #pragma unroll
                for (int q = 0; q < 4; q++) acc[nt][mt][q] = 0.f;

        #pragma unroll 4
        for (int ks = 0; ks < 16; ks++) {
            const int k0 = ks * 8;
            // ---- A fragments: one LDS.128 per mt (broadcast across warps) ----
            uint32_t aH[4][4];
            #pragma unroll
            for (int mt = 0; mt < 4; mt++) {
                float4 af = *reinterpret_cast<const float4*>(
                    &Aperm[lane * LSTRIDE + mt * 64 + ks * 4]);
                aH[mt][0] = __float_as_uint(af.x);
                aH[mt][1] = __float_as_uint(af.y);
                aH[mt][2] = __float_as_uint(af.z);
                aH[mt][3] = __float_as_uint(af.w);
            }
            #pragma unroll
            for (int nt = 0; nt < 4; nt++) {
                int code = n0 + nt * 8 + r_lane;
                const float* ep = embed + (size_t)code * DIM + k0 + c_lane;
                uint32_t bh0 = tf32_of(__ldg(ep));
                uint32_t bh1 = tf32_of(__ldg(ep + 4));
                #pragma unroll
                for (int mt = 0; mt < 4; mt++)
                    MMA_TF32(acc[nt][mt], aH[mt], bh0, bh1);
            }
        }

        // ---- branchless packed top-2 epilogue ----
        #pragma unroll
        for (int nt = 0; nt < 4; nt++) {
            int kk0 = n0 + nt * 8 + 2 * c_lane;
            #pragma unroll
            for (int mt = 0; mt < 4; mt++) {
                int rlo = mt * 16 + r_lane;
                float r2a = rn2s[rlo];
                float r2b = rn2s[rlo + 8];
                #pragma unroll
                for (int q = 0; q < 4; q++) {
                    int   h  = q >> 1;
                    int   kk = kk0 + (q & 1);
                    float r2 = h ? r2b : r2a;
                    float t  = __fsub_rn(__fadd_rn(r2, en2s[kk]),
                                         __fmul_rn(2.0f, acc[nt][mt][q]));
                    unsigned long long p =
                        ((unsigned long long)__float_as_uint(t) << 32) | (unsigned)kk;
                    unsigned long long hi = umax64(b1[mt][h], p);
                    b1[mt][h] = umin64(b1[mt][h], p);
                    b2[mt][h] = umin64(b2[mt][h], hi);
                }
            }
        }
    }

    // ---- per-warp packed min per token row (4-lane c_lane groups) ----
    #pragma unroll
    for (int mt = 0; mt < 4; mt++)
        #pragma unroll
        for (int h = 0; h < 2; h++) {
            unsigned long long v = b1[mt][h];
            #pragma unroll
            for (int off = 1; off <= 2; off <<= 1)
                v = umin64(v, __shfl_xor_sync(0xffffffffu, v, off));
            if (c_lane == 0) redp[wid][mt * 16 + r_lane + 8 * h] = v;
        }
    __syncthreads();

    if (tid < BM) {
        unsigned long long v = redp[0][tid];
        #pragma unroll
        for (int w = 1; w < 4; w++) v = umin64(v, redp[w][tid]);
        minv[tid] = __uint_as_float((uint32_t)(v >> 32));
        cand[tid] = ~0ull;
    }
    __syncthreads();

    // ---- exact rescoring of all candidates within MARGIN of approx min ----
    #pragma unroll
    for (int mt = 0; mt < 4; mt++)
        #pragma unroll
        for (int h = 0; h < 2; h++) {
            int row = mt * 16 + r_lane + 8 * h;
            float cut = minv[row] + MARGIN;
            const float4* srow4 = src4 + (size_t)row * (DIM / 4);
            float v1 = __uint_as_float((uint32_t)(b1[mt][h] >> 32));
            float v2 = __uint_as_float((uint32_t)(b2[mt][h] >> 32));
            if (v1 <= cut)
                rescore(srow4, embed, en2s, rn2s, cand, row,
                        (int)(unsigned)(b1[mt][h] & 0xFFFFFFFFull));
            if (v2 <= cut)
                rescore(srow4, embed, en2s, rn2s, cand, row,
                        (int)(unsigned)(b2[mt][h] & 0xFFFFFFFFull));
        }
    __syncthreads();

    if (tid < BM)
        idx_out[m0blk + tid] = (float)(unsigned)(cand[tid] & 0xFFFFFFFFull);
}

// ---------------------------------------------------------------------------
// residual: dst = src - gather(e[idx]), exact fsub. dst may alias src.
// ---------------------------------------------------------------------------
__global__ void __launch_bounds__(256)
residual_kernel(const float* __restrict__ src,
                const float* __restrict__ embed,
                const float* __restrict__ idx_lvl,
                float* __restrict__ dst,
                int early)
{
    if (early) return;
    int i = blockIdx.x * 256 + threadIdx.x;
    int row = i >> 5, c = i & 31;
    int k = __float2int_rn(idx_lvl[row]);
    float4 v = reinterpret_cast<const float4*>(src)[i];
    float4 e = reinterpret_cast<const float4*>(embed + (size_t)k * DIM)[c];
    v.x = __fsub_rn(v.x, e.x);
    v.y = __fsub_rn(v.y, e.y);
    v.z = __fsub_rn(v.z, e.z);
    v.w = __fsub_rn(v.w, e.w);
    reinterpret_cast<float4*>(dst)[i] = v;
}

__global__ void init3_kernel(float* __restrict__ out3, int early)
{
    if (early) return;
    if (threadIdx.x < 3) out3[threadIdx.x] = 0.f;
}

// ---------------------------------------------------------------------------
// final fused pass (unchanged from the validated R7 kernel)
// ---------------------------------------------------------------------------
__global__ void __launch_bounds__(256)
final_kernel(const float* __restrict__ inputs,
             const float* __restrict__ embedding,
             const float* __restrict__ idx_all,
             float* __restrict__ out_q,
             float* __restrict__ out3,
             int early)
{
    if (early) return;
    __shared__ float red[256];

    int tid = threadIdx.x;
    int d   = tid & 127;
    float acc = 0.f;

    #pragma unroll
    for (int it = 0; it < FINAL_ROWS / 2; it++) {
        int row = blockIdx.x * FINAL_ROWS + it * 2 + (tid >> 7);
        size_t o = (size_t)row * DIM + d;
        float inp = inputs[o];
        float r = inp, qs, e, diff;
        int k;

        k = __float2int_rn(idx_all[row]);
        e = embedding[((size_t)0 * NCODE + k) * DIM + d];
        diff = __fsub_rn(e, r); acc = fmaf(diff, diff, acc);
        qs = e; r = __fsub_rn(r, e);

        k = __float2int_rn(idx_all[(size_t)1 * NTOK + row]);
        e = embedding[((size_t)1 * NCODE + k) * DIM + d];
        diff = __fsub_rn(e, r); acc = fmaf(diff, diff, acc);
        qs = __fadd_rn(qs, e); r = __fsub_rn(r, e);

        k = __float2int_rn(idx_all[(size_t)2 * NTOK + row]);
        e = embedding[((size_t)2 * NCODE + k) * DIM + d];
        diff = __fsub_rn(e, r); acc = fmaf(diff, diff, acc);
        qs = __fadd_rn(qs, e); r = __fsub_rn(r, e);

        k = __float2int_rn(idx_all[(size_t)3 * NTOK + row]);
        e = embedding[((size_t)3 * NCODE + k) * DIM + d];
        diff = __fsub_rn(e, r); acc = fmaf(diff, diff, acc);
        qs = __fadd_rn(qs, e);

        out_q[o] = __fadd_rn(inp, __fsub_rn(qs, inp));
    }

    red[tid] = acc;
    __syncthreads();
    #pragma unroll
    for (int s = 128; s > 0; s >>= 1) {
        if (tid < s) red[tid] += red[tid + s];
        __syncthreads();
    }
    if (tid == 0) atomicAdd(&out3[1], red[0]);
}

__global__ void scalars_kernel(float* __restrict__ out3, int early)
{
    if (early) return;
    if (threadIdx.x == 0) {
        float cb = __fmul_rn(out3[1], 1.0f / 16777216.0f);
        out3[0] = __fadd_rn(cb, __fmul_rn(0.25f, cb));
        out3[1] = cb;
        out3[2] = cb;
    }
}

// ---------------------------------------------------------------------------
namespace {
struct ModuleEagerLoad {
    ModuleEagerLoad() {
        cudaFree(0);
        size_t f0 = 0, f1 = 0, tot = 0;
        cudaMemGetInfo(&f0, &tot);

        void* p;
        cudaGetSymbolAddress(&p, g_en2);

        prep_kernel<<<PREP_GRID, 256>>>(nullptr, 1);
        argmin_kernel<<<ARGMIN_GRID, 128>>>(nullptr, nullptr, nullptr, nullptr, 1);
        residual_kernel<<<RES_GRID, 256>>>(nullptr, nullptr, nullptr, nullptr, 1);
        init3_kernel<<<1, 32>>>(nullptr, 1);
        final_kernel<<<FINAL_GRID, 256>>>(nullptr, nullptr, nullptr, nullptr, nullptr, 1);
        scalars_kernel<<<1, 32>>>(nullptr, 1);
        cudaDeviceSynchronize();

        cudaMemGetInfo(&f1, &tot);
        fprintf(stderr, "[eager] free before=%zu after=%zu delta=%lld\n",
                f0, f1, (long long)f0 - (long long)f1);
    }
};
static ModuleEagerLoad s_eager_load;
}  // namespace

// ---------------------------------------------------------------------------
extern "C" void kernel_launch(void* const* d_in, const int* in_sizes, int n_in,
                              void* d_out, int out_size)
{
    const float* inputs    = (const float*)d_in[0];
    const float* embedding = (const float*)d_in[1];

    float* out     = (float*)d_out;
    float* out_q   = out;                            // N*D: residual scratch, then quantized_sum
    float* out_idx = out + (size_t)NTOK * DIM;       // L*N indices (as f32)
    float* out3    = out_idx + (size_t)NLVL * NTOK;  // vq, codebook, commit

    float* en2_base = nullptr;
    cudaGetSymbolAddress((void**)&en2_base, g_en2);

    init3_kernel<<<1, 32>>>(out3, 0);
    prep_kernel<<<PREP_GRID, 256>>>(embedding, 0);
    for (int lvl = 0; lvl < NLVL; lvl++) {
        const float* emb_l = embedding + (size_t)lvl * NCODE * DIM;
        const float* src   = (lvl == 0) ? inputs : out_q;
        argmin_kernel<<<ARGMIN_GRID, 128>>>(
            src, emb_l, en2_base + (size_t)lvl * NCODE,
            out_idx + (size_t)lvl * NTOK, 0);
        if (lvl < NLVL - 1)
            residual_kernel<<<RES_GRID, 256>>>(
                src, emb_l, out_idx + (size_t)lvl * NTOK, out_q, 0);
    }
    final_kernel<<<FINAL_GRID, 256>>>(inputs, embedding, out_idx, out_q, out3, 0);
    scalars_kernel<<<1, 32>>>(out3, 0);
}

// round 13
// speedup vs baseline: 2.0110x; 1.0111x over previous
#include <cuda_runtime.h>
#include <cstdint>
#include <cstdio>

#define NTOK  131072
#define DIM   128
#define NCODE 1024
#define NLVL  4

#define BM    64                 // tokens per CTA
#define ARGMIN_GRID (NTOK / BM)  // 2048
#define RES_GRID    (NTOK * (DIM / 4) / 256)     // 16384
#define FINAL_ROWS  16
#define FINAL_GRID  (NTOK / FINAL_ROWS)          // 8192
#define PREP_GRID   (NLVL * NCODE / 8)           // 512

#define MARGIN 2e-4f             // capture margin in s-domain (2x trunc error)

#define LSTRIDE 260              // Aperm per-lane stride (words): 260 % 32 == 4

// ---- small float-only device global (validated safe in R12) ----
__device__ float g_en2[NLVL * NCODE];   // 16 KB

// ---- legacy tensor-core mma (sm_80+; compiles on sm_100 base) ----
#define MMA_TF32(d, a, b0, b1)                                              \
    asm volatile("mma.sync.aligned.m16n8k8.row.col.f32.tf32.tf32.f32 "      \
        "{%0,%1,%2,%3}, {%4,%5,%6,%7}, {%8,%9}, {%0,%1,%2,%3};"             \
        : "+f"((d)[0]), "+f"((d)[1]), "+f"((d)[2]), "+f"((d)[3])            \
        : "r"((a)[0]), "r"((a)[1]), "r"((a)[2]), "r"((a)[3]),               \
          "r"(b0), "r"(b1))

__device__ __forceinline__ uint32_t tf32_of(float x)
{
    uint32_t h;
    asm("cvt.rna.tf32.f32 %0, %1;" : "=r"(h) : "f"(x));
    return h;
}

__device__ __forceinline__ unsigned long long umin64(unsigned long long a,
                                                     unsigned long long b)
{ return a < b ? a : b; }
__device__ __forceinline__ unsigned long long umax64(unsigned long long a,
                                                     unsigned long long b)
{ return a > b ? a : b; }

// ---------------------------------------------------------------------------
// prep: en2[r] = sum_d e[r][d]^2 for ALL levels, once per launch.
// Formula bit-identical to the validated R7/R11 version.
// ---------------------------------------------------------------------------
__global__ void __launch_bounds__(256)
prep_kernel(const float* __restrict__ embedding, int early)
{
    if (early) return;
    int lane = threadIdx.x & 31;
    int row  = blockIdx.x * 8 + (threadIdx.x >> 5);   // 0..4095
    float4 v = reinterpret_cast<const float4*>(embedding + (size_t)row * DIM)[lane];
    float p = __fadd_rn(__fadd_rn(__fadd_rn(__fmul_rn(v.x, v.x),
                                            __fmul_rn(v.y, v.y)),
                                  __fmul_rn(v.z, v.z)),
                        __fmul_rn(v.w, v.w));
    #pragma unroll
    for (int off = 16; off >= 1; off >>= 1)
        p = __fadd_rn(p, __shfl_down_sync(0xffffffffu, p, off));
    if (lane == 0) g_en2[row] = p;
}

// exact R7-bit-identical rescore: sequential-d fp32 fmaf dot + binned dist;
// lowest-index tie-break via packed u64 atomicMin (exact dist domain).
__device__ __forceinline__ void rescore(const float4* __restrict__ srow4,
                                        const float* __restrict__ embed,
                                        const float* en2s, const float* rn2s,
                                        unsigned long long* cand,
                                        int row, int k)
{
    const float4* e4 = reinterpret_cast<const float4*>(embed + (size_t)k * DIM);
    float dot = 0.f;
    #pragma unroll 8
    for (int i = 0; i < 32; i++) {
        float4 a = __ldg(srow4 + i);
        float4 e = __ldg(e4 + i);
        dot = fmaf(a.x, e.x, dot);
        dot = fmaf(a.y, e.y, dot);
        dot = fmaf(a.z, e.z, dot);
        dot = fmaf(a.w, e.w, dot);
    }
    float dist = __fsub_rn(__fadd_rn(rn2s[row], en2s[k]), __fmul_rn(2.0f, dot));
    unsigned long long p =
        ((unsigned long long)__float_as_uint(dist) << 32) | (unsigned)k;
    atomicMin(cand + row, p);
}

// ---------------------------------------------------------------------------
// argmin: 1xTF32 mma.sync with the distance bias FOLDED INTO the GEMM via two
// extra K-columns (b=-128 exact, b=-en2/2). s = -2*acc = 256 + en2 - 2*dot > 0
// so raw float bits are order-monotone. B operands are raw fp32 bits
// (HW tf32 truncation); exact rescoring absorbs all approx error.
// ---------------------------------------------------------------------------
__global__ void __launch_bounds__(128)
argmin_kernel(const float* __restrict__ src,     // N x D (inputs or residual)
              const float* __restrict__ embed,   // K x D, this level (fp32)
              const float* __restrict__ en2g,    // K, this level (from g_en2)
              float* __restrict__ idx_out,       // N floats, this level slice
              int early)
{
    if (early) return;

    __shared__ uint32_t Aperm[32 * LSTRIDE];     // 33.3 KB fragment-major tf32
    __shared__ float en2s[NCODE];                // 4 KB
    __shared__ float rn2s[BM];
    __shared__ unsigned long long redp[4][BM];   // per-warp packed approx min
    __shared__ float minv[BM];
    __shared__ unsigned long long cand[BM];

    const int tid  = threadIdx.x;
    const int wid  = tid >> 5, lane = tid & 31;
    const int m0blk = blockIdx.x * BM;
    const float4* __restrict__ src4 =
        reinterpret_cast<const float4*>(src) + (size_t)m0blk * (DIM / 4);

    // ---- en2 slice: global -> smem (coalesced float4) ----
    {
        const float4* g4 = reinterpret_cast<const float4*>(en2g);
        float4* s4 = reinterpret_cast<float4*>(en2s);
        for (int j = tid; j < NCODE / 4; j += 128) s4[j] = __ldg(g4 + j);
    }

    // ---- A panel -> Aperm (tf32 RN-rounded, mma-fragment-major layout) ----
    #pragma unroll
    for (int i = 0; i < 16; i++) {
        int flat = tid + i * 128;
        int row = flat >> 5, c4 = flat & 31;
        float4 v = src4[(size_t)row * (DIM / 4) + c4];
        int ks = c4 >> 1, colhalf = c4 & 1;
        int r_lane = row & 7, rowhalf = (row >> 3) & 1, mt = row >> 4;
        int q = rowhalf + 2 * colhalf;
        int base = (r_lane * 4) * LSTRIDE + mt * 64 + ks * 4 + q;
        Aperm[base + 0 * LSTRIDE] = tf32_of(v.x);
        Aperm[base + 1 * LSTRIDE] = tf32_of(v.y);
        Aperm[base + 2 * LSTRIDE] = tf32_of(v.z);
        Aperm[base + 3 * LSTRIDE] = tf32_of(v.w);
    }

    // ---- rn2 from EXACT global values: bit-identical to R7 ----
    for (int r = wid; r < BM; r += 4) {
        float4 v = src4[(size_t)r * (DIM / 4) + lane];
        float p = __fadd_rn(__fadd_rn(__fadd_rn(__fmul_rn(v.x, v.x),
                                                __fmul_rn(v.y, v.y)),
                                      __fmul_rn(v.z, v.z)),
                            __fmul_rn(v.w, v.w));
        #pragma unroll
        for (int off = 16; off >= 1; off >>= 1)
            p = __fadd_rn(p, __shfl_down_sync(0xffffffffu, p, off));
        if (lane == 0) rn2s[r] = p;
    }
    __syncthreads();

    const int r_lane = lane >> 2;   // 0..7
    const int c_lane = lane & 3;    // 0..3
    const int n_warp0 = wid * 256;  // this warp's code range

    // extra-K A fragments: a(m, k=0)=a(m, k=1)=1 -> frags 0,1 for c_lane<=1
    uint32_t aHe[4];
    aHe[0] = aHe[1] = (c_lane <= 1) ? __float_as_uint(1.0f) : 0u;
    aHe[2] = aHe[3] = 0u;

    // per-thread packed top-2 in s-domain (s bits<<32 | idx)
    unsigned long long b1[4][2], b2[4][2];
    #pragma unroll
    for (int mt = 0; mt < 4; mt++)
        #pragma unroll
        for (int h = 0; h < 2; h++) { b1[mt][h] = ~0ull; b2[mt][h] = ~0ull; }

    for (int nblk = 0; nblk < 8; nblk++) {
        const int n0 = n_warp0 + nblk * 32;

        float acc[4][4][4];   // [nt][mt][frag]
        #pragma unroll
        for (int nt = 0; nt < 4; nt++)
            #pragma unroll
            for (int mt = 0; mt < 4; mt++)
                #pragma unroll
                for (int q = 0; q < 4; q++) acc[nt][mt][q] = 0.f;

        #pragma unroll 4
        for (int ks = 0; ks < 16; ks++) {
            const int k0 = ks * 8;
            uint32_t aH[4][4];
            #pragma unroll
            for (int mt = 0; mt < 4; mt++) {
                float4 af = *reinterpret_cast<const float4*>(
                    &Aperm[lane * LSTRIDE + mt * 64 + ks * 4]);
                aH[mt][0] = __float_as_uint(af.x);
                aH[mt][1] = __float_as_uint(af.y);
                aH[mt][2] = __float_as_uint(af.z);
                aH[mt][3] = __float_as_uint(af.w);
            }
            #pragma unroll
            for (int nt = 0; nt < 4; nt++) {
                int code = n0 + nt * 8 + r_lane;
                const float* ep = embed + (size_t)code * DIM + k0 + c_lane;
                uint32_t bh0 = __float_as_uint(__ldg(ep));       // raw bits,
                uint32_t bh1 = __float_as_uint(__ldg(ep + 4));   // HW truncates
                #pragma unroll
                for (int mt = 0; mt < 4; mt++)
                    MMA_TF32(acc[nt][mt], aH[mt], bh0, bh1);
            }
        }

        // ---- extra K-group: fold bias (k=0: -128 exact, k=1: -en2/2) ----
        #pragma unroll
        for (int nt = 0; nt < 4; nt++) {
            int code = n0 + nt * 8 + r_lane;
            uint32_t bh0 = 0u;
            if (c_lane == 0) bh0 = __float_as_uint(-128.0f);
            if (c_lane == 1) bh0 = __float_as_uint(__fmul_rn(-0.5f, en2s[code]));
            #pragma unroll
            for (int mt = 0; mt < 4; mt++)
                MMA_TF32(acc[nt][mt], aHe, bh0, 0u);
        }

        // ---- slim epilogue: s = -2*acc (>0), packed top-2 ----
        #pragma unroll
        for (int nt = 0; nt < 4; nt++) {
            int kk0 = n0 + nt * 8 + 2 * c_lane;
            #pragma unroll
            for (int mt = 0; mt < 4; mt++) {
                #pragma unroll
                for (int q = 0; q < 4; q++) {
                    int   h  = q >> 1;
                    int   kk = kk0 + (q & 1);
                    float s  = __fmul_rn(-2.0f, acc[nt][mt][q]);
                    unsigned long long p =
                        ((unsigned long long)__float_as_uint(s) << 32) | (unsigned)kk;
                    unsigned long long hi = umax64(b1[mt][h], p);
                    b1[mt][h] = umin64(b1[mt][h], p);
                    b2[mt][h] = umin64(b2[mt][h], hi);
                }
            }
        }
    }

    // ---- per-warp packed min per token row ----
    #pragma unroll
    for (int mt = 0; mt < 4; mt++)
        #pragma unroll
        for (int h = 0; h < 2; h++) {
            unsigned long long v = b1[mt][h];
            #pragma unroll
            for (int off = 1; off <= 2; off <<= 1)
                v = umin64(v, __shfl_xor_sync(0xffffffffu, v, off));
            if (c_lane == 0) redp[wid][mt * 16 + r_lane + 8 * h] = v;
        }
    __syncthreads();

    if (tid < BM) {
        unsigned long long v = redp[0][tid];
        #pragma unroll
        for (int w = 1; w < 4; w++) v = umin64(v, redp[w][tid]);
        minv[tid] = __uint_as_float((uint32_t)(v >> 32));   // min s
        cand[tid] = ~0ull;
    }
    __syncthreads();

    // ---- exact rescoring of candidates within MARGIN (s-domain cut) ----
    #pragma unroll
    for (int mt = 0; mt < 4; mt++)
        #pragma unroll
        for (int h = 0; h < 2; h++) {
            int row = mt * 16 + r_lane + 8 * h;
            float cut = minv[row] + MARGIN;
            const float4* srow4 = src4 + (size_t)row * (DIM / 4);
            float v1 = __uint_as_float((uint32_t)(b1[mt][h] >> 32));
            float v2 = __uint_as_float((uint32_t)(b2[mt][h] >> 32));
            if (v1 <= cut)
                rescore(srow4, embed, en2s, rn2s, cand, row,
                        (int)(unsigned)(b1[mt][h] & 0xFFFFFFFFull));
            if (v2 <= cut)
                rescore(srow4, embed, en2s, rn2s, cand, row,
                        (int)(unsigned)(b2[mt][h] & 0xFFFFFFFFull));
        }
    __syncthreads();

    if (tid < BM)
        idx_out[m0blk + tid] = (float)(unsigned)(cand[tid] & 0xFFFFFFFFull);
}

// ---------------------------------------------------------------------------
// residual: dst = src - gather(e[idx]), exact fsub. dst may alias src.
// ---------------------------------------------------------------------------
__global__ void __launch_bounds__(256)
residual_kernel(const float* __restrict__ src,
                const float* __restrict__ embed,
                const float* __restrict__ idx_lvl,
                float* __restrict__ dst,
                int early)
{
    if (early) return;
    int i = blockIdx.x * 256 + threadIdx.x;
    int row = i >> 5, c = i & 31;
    int k = __float2int_rn(idx_lvl[row]);
    float4 v = reinterpret_cast<const float4*>(src)[i];
    float4 e = reinterpret_cast<const float4*>(embed + (size_t)k * DIM)[c];
    v.x = __fsub_rn(v.x, e.x);
    v.y = __fsub_rn(v.y, e.y);
    v.z = __fsub_rn(v.z, e.z);
    v.w = __fsub_rn(v.w, e.w);
    reinterpret_cast<float4*>(dst)[i] = v;
}

__global__ void init3_kernel(float* __restrict__ out3, int early)
{
    if (early) return;
    if (threadIdx.x < 3) out3[threadIdx.x] = 0.f;
}

// ---------------------------------------------------------------------------
// final fused pass (unchanged from the validated R7 kernel)
// ---------------------------------------------------------------------------
__global__ void __launch_bounds__(256)
final_kernel(const float* __restrict__ inputs,
             const float* __restrict__ embedding,
             const float* __restrict__ idx_all,
             float* __restrict__ out_q,
             float* __restrict__ out3,
             int early)
{
    if (early) return;
    __shared__ float red[256];

    int tid = threadIdx.x;
    int d   = tid & 127;
    float acc = 0.f;

    #pragma unroll
    for (int it = 0; it < FINAL_ROWS / 2; it++) {
        int row = blockIdx.x * FINAL_ROWS + it * 2 + (tid >> 7);
        size_t o = (size_t)row * DIM + d;
        float inp = inputs[o];
        float r = inp, qs, e, diff;
        int k;

        k = __float2int_rn(idx_all[row]);
        e = embedding[((size_t)0 * NCODE + k) * DIM + d];
        diff = __fsub_rn(e, r); acc = fmaf(diff, diff, acc);
        qs = e; r = __fsub_rn(r, e);

        k = __float2int_rn(idx_all[(size_t)1 * NTOK + row]);
        e = embedding[((size_t)1 * NCODE + k) * DIM + d];
        diff = __fsub_rn(e, r); acc = fmaf(diff, diff, acc);
        qs = __fadd_rn(qs, e); r = __fsub_rn(r, e);

        k = __float2int_rn(idx_all[(size_t)2 * NTOK + row]);
        e = embedding[((size_t)2 * NCODE + k) * DIM + d];
        diff = __fsub_rn(e, r); acc = fmaf(diff, diff, acc);
        qs = __fadd_rn(qs, e); r = __fsub_rn(r, e);

        k = __float2int_rn(idx_all[(size_t)3 * NTOK + row]);
        e = embedding[((size_t)3 * NCODE + k) * DIM + d];
        diff = __fsub_rn(e, r); acc = fmaf(diff, diff, acc);
        qs = __fadd_rn(qs, e);

        out_q[o] = __fadd_rn(inp, __fsub_rn(qs, inp));
    }

    red[tid] = acc;
    __syncthreads();
    #pragma unroll
    for (int s = 128; s > 0; s >>= 1) {
        if (tid < s) red[tid] += red[tid + s];
        __syncthreads();
    }
    if (tid == 0) atomicAdd(&out3[1], red[0]);
}

__global__ void scalars_kernel(float* __restrict__ out3, int early)
{
    if (early) return;
    if (threadIdx.x == 0) {
        float cb = __fmul_rn(out3[1], 1.0f / 16777216.0f);
        out3[0] = __fadd_rn(cb, __fmul_rn(0.25f, cb));
        out3[1] = cb;
        out3[2] = cb;
    }
}

// ---------------------------------------------------------------------------
namespace {
struct ModuleEagerLoad {
    ModuleEagerLoad() {
        cudaFree(0);
        size_t f0 = 0, f1 = 0, tot = 0;
        cudaMemGetInfo(&f0, &tot);

        void* p;
        cudaGetSymbolAddress(&p, g_en2);

        prep_kernel<<<PREP_GRID, 256>>>(nullptr, 1);
        argmin_kernel<<<ARGMIN_GRID, 128>>>(nullptr, nullptr, nullptr, nullptr, 1);
        residual_kernel<<<RES_GRID, 256>>>(nullptr, nullptr, nullptr, nullptr, 1);
        init3_kernel<<<1, 32>>>(nullptr, 1);
        final_kernel<<<FINAL_GRID, 256>>>(nullptr, nullptr, nullptr, nullptr, nullptr, 1);
        scalars_kernel<<<1, 32>>>(nullptr, 1);
        cudaDeviceSynchronize();

        cudaMemGetInfo(&f1, &tot);
        fprintf(stderr, "[eager] free before=%zu after=%zu delta=%lld\n",
                f0, f1, (long long)f0 - (long long)f1);
    }
};
static ModuleEagerLoad s_eager_load;
}  // namespace

// ---------------------------------------------------------------------------
extern "C" void kernel_launch(void* const* d_in, const int* in_sizes, int n_in,
                              void* d_out, int out_size)
{
    const float* inputs    = (const float*)d_in[0];
    const float* embedding = (const float*)d_in[1];

    float* out     = (float*)d_out;
    float* out_q   = out;                            // N*D: residual scratch, then quantized_sum
    float* out_idx = out + (size_t)NTOK * DIM;       // L*N indices (as f32)
    float* out3    = out_idx + (size_t)NLVL * NTOK;  // vq, codebook, commit

    float* en2_base = nullptr;
    cudaGetSymbolAddress((void**)&en2_base, g_en2);

    init3_kernel<<<1, 32>>>(out3, 0);
    prep_kernel<<<PREP_GRID, 256>>>(embedding, 0);
    for (int lvl = 0; lvl < NLVL; lvl++) {
        const float* emb_l = embedding + (size_t)lvl * NCODE * DIM;
        const float* src   = (lvl == 0) ? inputs : out_q;
        argmin_kernel<<<ARGMIN_GRID, 128>>>(
            src, emb_l, en2_base + (size_t)lvl * NCODE,
            out_idx + (size_t)lvl * NTOK, 0);
        if (lvl < NLVL - 1)
            residual_kernel<<<RES_GRID, 256>>>(
                src, emb_l, out_idx + (size_t)lvl * NTOK, out_q, 0);
    }
    final_kernel<<<FINAL_GRID, 256>>>(inputs, embedding, out_idx, out_q, out3, 0);
    scalars_kernel<<<1, 32>>>(out3, 0);
}